// round 9
// baseline (speedup 1.0000x reference)
#include <cuda_runtime.h>
#include <cuda_fp16.h>
#include <cstdint>

// ---------------------------------------------------------------------------
// Fused persistent LSTM classifier, v8 = R4 (447us) skeleton +
//  (1) half2 activations: tanh.approx.f16x2, MUFU 10 -> 5 per thread/step;
//      c-state stays fp32; h produced directly as half2.
//  (2) mild accumulator split (L0 depth 12->8, L1 8->4), register-funded by
//      loading bias init from smem each step instead of keeping it in regs.
// Sync topology, x pipeline, staging, head: identical to R4.
// ---------------------------------------------------------------------------

namespace {

constexpr int T_ = 512, I_ = 128, H_ = 64, E_ = 128, C_ = 100;
constexpr int BT = 8, NCTA = 128, NTHR = 512;

constexpr int SWI = 136;
constexpr int SWH = 72;
constexpr int SXS = 136;
constexpr int SHS = 72;

constexpr int OFF_WIH0 = 0;
constexpr int OFF_WHH0 = 69632;
constexpr int OFF_WIH1 = 106496;
constexpr int OFF_WHH1 = 143360;
constexpr int OFF_B0   = 180224;
constexpr int OFF_B1   = 181248;
constexpr int OFF_X    = 182272;   // 2 bufs * 2176B
constexpr int OFF_H0   = 186624;   // 2 bufs * 1152B
constexpr int OFF_H1   = 188928;
constexpr int OFF_HF   = 191232;
constexpr int OFF_E    = 193280;
constexpr int OFF_F    = 197376;
constexpr int SMEM_TOTAL = 201472;

#define BARRIER() asm volatile("bar.sync 0;" ::: "memory")

__device__ __forceinline__ half2 tanh2(half2 x) {
    uint32_t xi = *reinterpret_cast<uint32_t*>(&x), y;
    asm("tanh.approx.f16x2 %0, %1;" : "=r"(y) : "r"(xi));
    return *reinterpret_cast<half2*>(&y);
}
__device__ __forceinline__ half2 sig2(half2 x) {
    const half2 hh = __float2half2_rn(0.5f);
    return __hfma2(tanh2(__hmul2(x, hh)), hh, hh);
}

// gates: a0[0,1]=i(n0,n0+1), a0[2,3]=f, a1[0,1]=g, a1[2,3]=o. c fp32.
__device__ __forceinline__ half2 cell2(const float a0[4], const float a1[4],
                                       float& ca, float& cb) {
    half2 hi = sig2(__floats2half2_rn(a0[0], a0[1]));
    half2 hf = sig2(__floats2half2_rn(a0[2], a0[3]));
    half2 hg = tanh2(__floats2half2_rn(a1[0], a1[1]));
    half2 ho = sig2(__floats2half2_rn(a1[2], a1[3]));
    float2 fi = __half22float2(hi);
    float2 ff = __half22float2(hf);
    float2 fg = __half22float2(hg);
    ca = ff.x * ca + fi.x * fg.x;
    cb = ff.y * cb + fi.y * fg.y;
    return __hmul2(ho, tanh2(__floats2half2_rn(ca, cb)));
}

__device__ __forceinline__ void mma4(float c[4], const uint32_t a[4],
                                     uint32_t b0, uint32_t b1) {
    asm volatile(
        "mma.sync.aligned.m16n8k16.row.col.f32.f16.f16.f32 "
        "{%0,%1,%2,%3},{%4,%5,%6,%7},{%8,%9},{%0,%1,%2,%3};\n"
        : "+f"(c[0]), "+f"(c[1]), "+f"(c[2]), "+f"(c[3])
        : "r"(a[0]), "r"(a[1]), "r"(a[2]), "r"(a[3]), "r"(b0), "r"(b1));
}

template <int KT, int S>
__device__ __forceinline__ void load_w(const half* __restrict__ sW, int wc, int g,
                                       int t, uint32_t f[KT][2][4]) {
#pragma unroll
    for (int kt = 0; kt < KT; kt++)
#pragma unroll
        for (int u = 0; u < 2; u++) {
            const half* p = sW + (wc * 32 + u * 16 + g) * S + kt * 16 + 2 * t;
            f[kt][u][0] = *(const uint32_t*)(p);
            f[kt][u][1] = *(const uint32_t*)(p + 8 * S);
            f[kt][u][2] = *(const uint32_t*)(p + 8);
            f[kt][u][3] = *(const uint32_t*)(p + 8 * S + 8);
        }
}

// acc init from bias in smem (4 LDS.32); aB zeroed
__device__ __forceinline__ void acc_init(float aA[2][4], float aB[2][4],
                                         const float* __restrict__ sBj) {
    float v00 = sBj[0], v01 = sBj[64], v10 = sBj[128], v11 = sBj[192];
    aA[0][0] = v00; aA[0][1] = v00; aA[0][2] = v01; aA[0][3] = v01;
    aA[1][0] = v10; aA[1][1] = v10; aA[1][2] = v11; aA[1][3] = v11;
#pragma unroll
    for (int u = 0; u < 2; u++)
#pragma unroll
        for (int e = 0; e < 4; e++) aB[u][e] = 0.f;
}

__global__ void __launch_bounds__(NTHR, 1)
lstm_fused(const float* __restrict__ x,
           const float* __restrict__ Wih0, const float* __restrict__ Whh0,
           const float* __restrict__ bih0, const float* __restrict__ bhh0,
           const float* __restrict__ Wih1, const float* __restrict__ Whh1,
           const float* __restrict__ bih1, const float* __restrict__ bhh1,
           const float* __restrict__ Wproj, const float* __restrict__ bproj,
           const float* __restrict__ Wfc1, const float* __restrict__ bfc1,
           const float* __restrict__ Wfc2, const float* __restrict__ bfc2,
           float* __restrict__ out)
{
    extern __shared__ unsigned char smem[];
    half*  sWih0 = (half*)(smem + OFF_WIH0);
    half*  sWhh0 = (half*)(smem + OFF_WHH0);
    half*  sWih1 = (half*)(smem + OFF_WIH1);
    half*  sWhh1 = (half*)(smem + OFF_WHH1);
    float* sB0   = (float*)(smem + OFF_B0);
    float* sB1   = (float*)(smem + OFF_B1);
    half*  sX    = (half*)(smem + OFF_X);
    half*  sH0   = (half*)(smem + OFF_H0);
    half*  sH1   = (half*)(smem + OFF_H1);
    float* sHF   = (float*)(smem + OFF_HF);
    float* sE    = (float*)(smem + OFF_E);
    float* sF    = (float*)(smem + OFF_F);

    const int tid  = threadIdx.x;
    const int lane = tid & 31;
    const int w    = tid >> 5;
    const int wc   = w & 7;
    const int g    = lane >> 2;
    const int t    = lane & 3;
    const int b0r  = blockIdx.x * BT;

    // ---- stage permuted fp16 weights + fused biases ----
    for (int i = tid; i < 256 * 128; i += NTHR) {
        int p = i >> 7, k = i & 127;
        int m = (((p >> 4) & 1) * 2 + ((p >> 3) & 1)) * 64 + (p >> 5) * 8 + (p & 7);
        sWih0[p * SWI + k] = __float2half(Wih0[m * 128 + k]);
    }
    for (int i = tid; i < 256 * 64; i += NTHR) {
        int p = i >> 6, k = i & 63;
        int m = (((p >> 4) & 1) * 2 + ((p >> 3) & 1)) * 64 + (p >> 5) * 8 + (p & 7);
        sWhh0[p * SWH + k] = __float2half(Whh0[m * 64 + k]);
        sWih1[p * SWH + k] = __float2half(Wih1[m * 64 + k]);
        sWhh1[p * SWH + k] = __float2half(Whh1[m * 64 + k]);
    }
    for (int i = tid; i < 256; i += NTHR) {
        sB0[i] = bih0[i] + bhh0[i];
        sB1[i] = bih1[i] + bhh1[i];
    }
    for (int i = tid; i < 2 * BT * SHS; i += NTHR)
        sH1[i] = __float2half(0.f);

    // ---- x prefetch owned by L1 warps: warp = batch row, lane = 4 floats ----
    const int xr = wc, xi = lane * 4;
    const float* xrow = x + ((size_t)(b0r + xr) * T_) * I_ + xi;
    float4 xpre = make_float4(0.f, 0.f, 0.f, 0.f);
    if (w >= 8) {
        float4 xv = *(const float4*)(xrow);            // x(0) -> buf1
        half* xw = sX + BT * SXS;
        *(half2*)(xw + xr * SXS + xi)     = __floats2half2_rn(xv.x, xv.y);
        *(half2*)(xw + xr * SXS + xi + 2) = __floats2half2_rn(xv.z, xv.w);
        xpre = *(const float4*)(xrow + I_);            // x(1)
    }
    __syncthreads();

    const int n0 = 2 * t;
    const int j  = wc * 8 + g;

    if (w < 8) {
        // ================= layer-0 warps =================
        uint32_t fih0[8][2][4], fhh0[4][2][4];
        load_w<8, SWI>(sWih0, wc, g, t, fih0);
        load_w<4, SWH>(sWhh0, wc, g, t, fhh0);
        const float* sB0j = sB0 + j;
        float c00 = 0.f, c01 = 0.f;

        {   // prologue: t=0 cell (no recurrent term)
            float aA[2][4], aB[2][4];
            acc_init(aA, aB, sB0j);
            const half* X = sX + BT * SXS;
#pragma unroll
            for (int kt = 0; kt < 8; kt++) {
                const half* p = X + g * SXS + kt * 16 + 2 * t;
                uint32_t b0 = *(const uint32_t*)(p);
                uint32_t b1 = *(const uint32_t*)(p + 8);
                float (*acc)[4] = (kt < 4) ? aA : aB;
                mma4(acc[0], fih0[kt][0], b0, b1);
                mma4(acc[1], fih0[kt][1], b0, b1);
            }
            float a0[4], a1[4];
#pragma unroll
            for (int e = 0; e < 4; e++) {
                a0[e] = aA[0][e] + aB[0][e];
                a1[e] = aA[1][e] + aB[1][e];
            }
            half2 h2 = cell2(a0, a1, c00, c01);
            sH0[n0 * SHS + j]       = __low2half(h2);
            sH0[(n0 + 1) * SHS + j] = __high2half(h2);
        }
        BARRIER();

        for (int k = 0; k < T_; k++) {
            const int p = k & 1;
            float aA[2][4], aB[2][4];
            acc_init(aA, aB, sB0j);
            const half* H0 = sH0 + p * (BT * SHS);
#pragma unroll
            for (int kt = 0; kt < 4; kt++) {        // hh -> aB (depth 4)
                const half* q = H0 + g * SHS + kt * 16 + 2 * t;
                uint32_t b0 = *(const uint32_t*)(q);
                uint32_t b1 = *(const uint32_t*)(q + 8);
                mma4(aB[0], fhh0[kt][0], b0, b1);
                mma4(aB[1], fhh0[kt][1], b0, b1);
            }
            const half* X = sX + p * (BT * SXS);
#pragma unroll
            for (int kt = 0; kt < 8; kt++) {        // ih: kt0-3 -> aA, kt4-7 -> aB
                const half* q = X + g * SXS + kt * 16 + 2 * t;
                uint32_t b0 = *(const uint32_t*)(q);
                uint32_t b1 = *(const uint32_t*)(q + 8);
                float (*acc)[4] = (kt < 4) ? aA : aB;
                mma4(acc[0], fih0[kt][0], b0, b1);
                mma4(acc[1], fih0[kt][1], b0, b1);
            }
            float a0[4], a1[4];
#pragma unroll
            for (int e = 0; e < 4; e++) {
                a0[e] = aA[0][e] + aB[0][e];
                a1[e] = aA[1][e] + aB[1][e];
            }
            half2 h2 = cell2(a0, a1, c00, c01);     // L0 cell, t = k+1
            half* h0w = sH0 + (1 - p) * (BT * SHS);
            h0w[n0 * SHS + j]       = __low2half(h2);
            h0w[(n0 + 1) * SHS + j] = __high2half(h2);
            BARRIER();
        }
    } else {
        // ================= layer-1 warps =================
        uint32_t fih1[4][2][4], fhh1[4][2][4];
        load_w<4, SWH>(sWih1, wc, g, t, fih1);
        load_w<4, SWH>(sWhh1, wc, g, t, fhh1);
        const float* sB1j = sB1 + j;
        float c10 = 0.f, c11 = 0.f;

        {   // commit x(1) -> buf0, fetch x(2)
            half* xw = sX;
            *(half2*)(xw + xr * SXS + xi)     = __floats2half2_rn(xpre.x, xpre.y);
            *(half2*)(xw + xr * SXS + xi + 2) = __floats2half2_rn(xpre.z, xpre.w);
            xpre = *(const float4*)(xrow + 2 * (size_t)I_);
        }
        BARRIER();

        for (int k = 0; k < T_; k++) {
            const int p = k & 1;
            {   // x pipeline: commit x(k+2) -> buf 1-p, launch LDG x(k+3)
                half* xw = sX + (1 - p) * (BT * SXS);
                *(half2*)(xw + xr * SXS + xi)     = __floats2half2_rn(xpre.x, xpre.y);
                *(half2*)(xw + xr * SXS + xi + 2) = __floats2half2_rn(xpre.z, xpre.w);
                int tn = k + 3; if (tn > T_ - 1) tn = T_ - 1;
                xpre = *(const float4*)(xrow + (size_t)tn * I_);
            }
            float aA[2][4], aB[2][4];
            acc_init(aA, aB, sB1j);
            const half* H0 = sH0 + p * (BT * SHS);
            const half* H1 = sH1 + p * (BT * SHS);
#pragma unroll
            for (int kt = 0; kt < 4; kt++) {        // ih(h0) -> aA, hh(h1) -> aB
                const half* q0 = H0 + g * SHS + kt * 16 + 2 * t;
                uint32_t b0 = *(const uint32_t*)(q0);
                uint32_t b1 = *(const uint32_t*)(q0 + 8);
                mma4(aA[0], fih1[kt][0], b0, b1);
                mma4(aA[1], fih1[kt][1], b0, b1);
                const half* q1 = H1 + g * SHS + kt * 16 + 2 * t;
                uint32_t d0 = *(const uint32_t*)(q1);
                uint32_t d1 = *(const uint32_t*)(q1 + 8);
                mma4(aB[0], fhh1[kt][0], d0, d1);
                mma4(aB[1], fhh1[kt][1], d0, d1);
            }
            float a0[4], a1[4];
#pragma unroll
            for (int e = 0; e < 4; e++) {
                a0[e] = aA[0][e] + aB[0][e];
                a1[e] = aA[1][e] + aB[1][e];
            }
            half2 h2 = cell2(a0, a1, c10, c11);     // L1 cell, t = k
            half* h1w = sH1 + (1 - p) * (BT * SHS);
            h1w[n0 * SHS + j]       = __low2half(h2);
            h1w[(n0 + 1) * SHS + j] = __high2half(h2);
            if (k == T_ - 1) {
                float2 hv = __half22float2(h2);
                sHF[n0 * H_ + j]       = hv.x;
                sHF[(n0 + 1) * H_ + j] = hv.y;
            }
            BARRIER();
        }
    }

    __syncthreads();

    // ---- head: proj -> relu -> fc1 -> relu -> fc2 ----
#pragma unroll
    for (int q = 0; q < 2; q++) {
        int idx = tid + q * NTHR;
        int r = idx >> 7, e = idx & 127;
        float a = bproj[e];
        const float* wp = Wproj + e * H_;
        const float* hp = sHF + r * H_;
#pragma unroll 8
        for (int kk = 0; kk < H_; kk++) a += hp[kk] * wp[kk];
        sE[r * E_ + e] = fmaxf(a, 0.f);
    }
    __syncthreads();
#pragma unroll
    for (int q = 0; q < 2; q++) {
        int idx = tid + q * NTHR;
        int r = idx >> 7, e = idx & 127;
        float a = bfc1[e];
        const float* wp = Wfc1 + e * E_;
        const float* hp = sE + r * E_;
#pragma unroll 8
        for (int kk = 0; kk < E_; kk++) a += hp[kk] * wp[kk];
        sF[r * E_ + e] = fmaxf(a, 0.f);
    }
    __syncthreads();
    for (int idx = tid; idx < BT * C_; idx += NTHR) {
        int r = idx / C_, c = idx - r * C_;
        float a = bfc2[c];
        const float* wp = Wfc2 + c * E_;
        const float* hp = sF + r * E_;
#pragma unroll 8
        for (int kk = 0; kk < E_; kk++) a += hp[kk] * wp[kk];
        out[(size_t)(b0r + r) * C_ + c] = a;
    }
}

}  // namespace

extern "C" void kernel_launch(void* const* d_in, const int* in_sizes, int n_in,
                              void* d_out, int out_size) {
    cudaFuncSetAttribute(lstm_fused, cudaFuncAttributeMaxDynamicSharedMemorySize,
                         SMEM_TOTAL);
    lstm_fused<<<NCTA, NTHR, SMEM_TOTAL>>>(
        (const float*)d_in[0],
        (const float*)d_in[1],  (const float*)d_in[2],
        (const float*)d_in[3],  (const float*)d_in[4],
        (const float*)d_in[5],  (const float*)d_in[6],
        (const float*)d_in[7],  (const float*)d_in[8],
        (const float*)d_in[9],  (const float*)d_in[10],
        (const float*)d_in[11], (const float*)d_in[12],
        (const float*)d_in[13], (const float*)d_in[14],
        (float*)d_out);
}

// round 10
// speedup vs baseline: 1.0728x; 1.0728x over previous
#include <cuda_runtime.h>
#include <cuda_fp16.h>
#include <cstdint>

// ---------------------------------------------------------------------------
// Fused persistent LSTM classifier, v9 = R4 (447us) + cross-barrier software
// pipelining. Lockstep bar.sync 0 per step kept; R4 bodies kept; f32 cell.
//  - L0: ih0 mma (x part, 16 of 24) issued PRE-barrier for the NEXT step;
//    post-barrier chain = LDS + 4-deep hh0 + cell.  x: 4-slot ring, committed
//    by L1 four steps ahead (2-step LDG slack).
//  - L1: retimed -1 step (h1(k-1) at step k); its ih1 mma likewise issued
//    pre-barrier. Epilogue computes h1(T-1).
//  - h0: 4-slot ring (needed by retimed L1). h1: 2-slot ring.
// ---------------------------------------------------------------------------

namespace {

constexpr int T_ = 512, I_ = 128, H_ = 64, E_ = 128, C_ = 100;
constexpr int BT = 8, NCTA = 128, NTHR = 512;

constexpr int SWI = 136;
constexpr int SWH = 72;
constexpr int SXS = 136;
constexpr int SHS = 72;
constexpr int XROW = BT * SXS;      // halves per x slot
constexpr int HROW = BT * SHS;      // halves per h slot

constexpr int OFF_WIH0 = 0;         // 69632
constexpr int OFF_WHH0 = 69632;     // 36864
constexpr int OFF_WIH1 = 106496;    // 36864
constexpr int OFF_WHH1 = 143360;    // 36864
constexpr int OFF_B0   = 180224;    // 1024
constexpr int OFF_B1   = 181248;    // 1024
constexpr int OFF_X    = 182272;    // 4 slots * 2176 = 8704
constexpr int OFF_H0   = 190976;    // 4 slots * 1152 = 4608
constexpr int OFF_H1   = 195584;    // 2 slots * 1152 = 2304
constexpr int OFF_HF   = 197888;    // 2048
constexpr int OFF_E    = 199936;    // 4096
constexpr int OFF_F    = 204032;    // 4096
constexpr int SMEM_TOTAL = 208128;

#define BARRIER() asm volatile("bar.sync 0;" ::: "memory")

__device__ __forceinline__ float tanh_ap(float x) {
    float y;
    asm("tanh.approx.f32 %0, %1;" : "=f"(y) : "f"(x));
    return y;
}
__device__ __forceinline__ float fsig(float x) {
    return fmaf(0.5f, tanh_ap(0.5f * x), 0.5f);
}

__device__ __forceinline__ void mma4(float c[4], const uint32_t a[4],
                                     uint32_t b0, uint32_t b1) {
    asm volatile(
        "mma.sync.aligned.m16n8k16.row.col.f32.f16.f16.f32 "
        "{%0,%1,%2,%3},{%4,%5,%6,%7},{%8,%9},{%0,%1,%2,%3};\n"
        : "+f"(c[0]), "+f"(c[1]), "+f"(c[2]), "+f"(c[3])
        : "r"(a[0]), "r"(a[1]), "r"(a[2]), "r"(a[3]), "r"(b0), "r"(b1));
}

template <int KT, int S>
__device__ __forceinline__ void load_w(const half* __restrict__ sW, int wc, int g,
                                       int t, uint32_t f[KT][2][4]) {
#pragma unroll
    for (int kt = 0; kt < KT; kt++)
#pragma unroll
        for (int u = 0; u < 2; u++) {
            const half* p = sW + (wc * 32 + u * 16 + g) * S + kt * 16 + 2 * t;
            f[kt][u][0] = *(const uint32_t*)(p);
            f[kt][u][1] = *(const uint32_t*)(p + 8 * S);
            f[kt][u][2] = *(const uint32_t*)(p + 8);
            f[kt][u][3] = *(const uint32_t*)(p + 8 * S + 8);
        }
}

__device__ __forceinline__ void acc_set(float a[2][4], const float b[2][2]) {
#pragma unroll
    for (int u = 0; u < 2; u++) {
        a[u][0] = b[u][0]; a[u][1] = b[u][0];
        a[u][2] = b[u][1]; a[u][3] = b[u][1];
    }
}

__global__ void __launch_bounds__(NTHR, 1)
lstm_fused(const float* __restrict__ x,
           const float* __restrict__ Wih0, const float* __restrict__ Whh0,
           const float* __restrict__ bih0, const float* __restrict__ bhh0,
           const float* __restrict__ Wih1, const float* __restrict__ Whh1,
           const float* __restrict__ bih1, const float* __restrict__ bhh1,
           const float* __restrict__ Wproj, const float* __restrict__ bproj,
           const float* __restrict__ Wfc1, const float* __restrict__ bfc1,
           const float* __restrict__ Wfc2, const float* __restrict__ bfc2,
           float* __restrict__ out)
{
    extern __shared__ unsigned char smem[];
    half*  sWih0 = (half*)(smem + OFF_WIH0);
    half*  sWhh0 = (half*)(smem + OFF_WHH0);
    half*  sWih1 = (half*)(smem + OFF_WIH1);
    half*  sWhh1 = (half*)(smem + OFF_WHH1);
    float* sB0   = (float*)(smem + OFF_B0);
    float* sB1   = (float*)(smem + OFF_B1);
    half*  sX    = (half*)(smem + OFF_X);
    half*  sH0   = (half*)(smem + OFF_H0);
    half*  sH1   = (half*)(smem + OFF_H1);
    float* sHF   = (float*)(smem + OFF_HF);
    float* sE    = (float*)(smem + OFF_E);
    float* sF    = (float*)(smem + OFF_F);

    const int tid  = threadIdx.x;
    const int lane = tid & 31;
    const int w    = tid >> 5;
    const int wc   = w & 7;
    const int g    = lane >> 2;
    const int t    = lane & 3;
    const int b0r  = blockIdx.x * BT;

    // ---- stage permuted fp16 weights + fused biases + x(0..3) + zero h1 ----
    for (int i = tid; i < 256 * 128; i += NTHR) {
        int p = i >> 7, k = i & 127;
        int m = (((p >> 4) & 1) * 2 + ((p >> 3) & 1)) * 64 + (p >> 5) * 8 + (p & 7);
        sWih0[p * SWI + k] = __float2half(Wih0[m * 128 + k]);
    }
    for (int i = tid; i < 256 * 64; i += NTHR) {
        int p = i >> 6, k = i & 63;
        int m = (((p >> 4) & 1) * 2 + ((p >> 3) & 1)) * 64 + (p >> 5) * 8 + (p & 7);
        sWhh0[p * SWH + k] = __float2half(Whh0[m * 64 + k]);
        sWih1[p * SWH + k] = __float2half(Wih1[m * 64 + k]);
        sWhh1[p * SWH + k] = __float2half(Whh1[m * 64 + k]);
    }
    for (int i = tid; i < 256; i += NTHR) {
        sB0[i] = bih0[i] + bhh0[i];
        sB1[i] = bih1[i] + bhh1[i];
    }
    for (int i = tid; i < 2 * HROW; i += NTHR)
        sH1[i] = __float2half(0.f);                       // h1(-1)=h1(-2)=0
    for (int i = tid; i < 4 * BT * 128; i += NTHR) {      // x(0..3) -> slots 0..3
        int s = i >> 10, rem = i & 1023;
        int r = rem >> 7, c = rem & 127;
        sX[s * XROW + r * SXS + c] =
            __float2half(x[((size_t)(b0r + r) * T_ + s) * I_ + c]);
    }
    __syncthreads();

    const int n0 = 2 * t;
    const int j  = wc * 8 + g;

    if (w < 8) {
        // ================= layer-0 warps =================
        uint32_t fih0[8][2][4], fhh0[4][2][4];
        load_w<8, SWI>(sWih0, wc, g, t, fih0);
        load_w<4, SWH>(sWhh0, wc, g, t, fhh0);
        float bb0[2][2];
#pragma unroll
        for (int u = 0; u < 2; u++)
#pragma unroll
            for (int v = 0; v < 2; v++)
                bb0[u][v] = sB0[(2 * u + v) * 64 + wc * 8 + g];

        float c00 = 0.f, c01 = 0.f;
        float acc[2][4];

        {   // prologue: h0(0) = cell(b0 + Wih0@x(0)) -> slot 0
            acc_set(acc, bb0);
#pragma unroll
            for (int kt = 0; kt < 8; kt++) {
                const half* q = sX + g * SXS + kt * 16 + 2 * t;
                uint32_t b0 = *(const uint32_t*)(q);
                uint32_t b1 = *(const uint32_t*)(q + 8);
                mma4(acc[0], fih0[kt][0], b0, b1);
                mma4(acc[1], fih0[kt][1], b0, b1);
            }
            float i0 = fsig(acc[0][0]), i1 = fsig(acc[0][1]);
            float g0 = tanh_ap(acc[1][0]), g1 = tanh_ap(acc[1][1]);
            float o0 = fsig(acc[1][2]), o1 = fsig(acc[1][3]);
            c00 = i0 * g0; c01 = i1 * g1;
            sH0[n0 * SHS + j]       = __float2half(o0 * tanh_ap(c00));
            sH0[(n0 + 1) * SHS + j] = __float2half(o1 * tanh_ap(c01));
            // carried acc for iter 0: b0 + Wih0 @ x(1)
            acc_set(acc, bb0);
#pragma unroll
            for (int kt = 0; kt < 8; kt++) {
                const half* q = sX + XROW + g * SXS + kt * 16 + 2 * t;
                uint32_t b0 = *(const uint32_t*)(q);
                uint32_t b1 = *(const uint32_t*)(q + 8);
                mma4(acc[0], fih0[kt][0], b0, b1);
                mma4(acc[1], fih0[kt][1], b0, b1);
            }
        }
        BARRIER();                                        // B(-1)

        for (int k = 0; k < T_; k++) {
            // post-barrier: hh0 @ h0(k) onto carried acc (4-deep) -> cell
            const half* H0r = sH0 + (k & 3) * HROW;
#pragma unroll
            for (int kt = 0; kt < 4; kt++) {
                const half* q = H0r + g * SHS + kt * 16 + 2 * t;
                uint32_t b0 = *(const uint32_t*)(q);
                uint32_t b1 = *(const uint32_t*)(q + 8);
                mma4(acc[0], fhh0[kt][0], b0, b1);
                mma4(acc[1], fhh0[kt][1], b0, b1);
            }
            {   // L0 cell -> h0(k+1) into slot (k+1)&3
                float i0 = fsig(acc[0][0]), i1 = fsig(acc[0][1]);
                float f0 = fsig(acc[0][2]), f1 = fsig(acc[0][3]);
                float g0 = tanh_ap(acc[1][0]), g1 = tanh_ap(acc[1][1]);
                float o0 = fsig(acc[1][2]), o1 = fsig(acc[1][3]);
                c00 = f0 * c00 + i0 * g0;
                c01 = f1 * c01 + i1 * g1;
                half* h0w = sH0 + ((k + 1) & 3) * HROW;
                h0w[n0 * SHS + j]       = __float2half(o0 * tanh_ap(c00));
                h0w[(n0 + 1) * SHS + j] = __float2half(o1 * tanh_ap(c01));
            }
            // pre-barrier: rebuild acc = b0 + Wih0 @ x(k+2)  (latency drains
            // into the barrier wait; consumed next iteration)
            acc_set(acc, bb0);
            const half* X = sX + ((k + 2) & 3) * XROW;
#pragma unroll
            for (int kt = 0; kt < 8; kt++) {
                const half* q = X + g * SXS + kt * 16 + 2 * t;
                uint32_t b0 = *(const uint32_t*)(q);
                uint32_t b1 = *(const uint32_t*)(q + 8);
                mma4(acc[0], fih0[kt][0], b0, b1);
                mma4(acc[1], fih0[kt][1], b0, b1);
            }
            BARRIER();                                    // B(k)
        }
    } else {
        // ================= layer-1 warps (retimed -1 step) =================
        uint32_t fih1[4][2][4], fhh1[4][2][4];
        load_w<4, SWH>(sWih1, wc, g, t, fih1);
        load_w<4, SWH>(sWhh1, wc, g, t, fhh1);
        float bb1[2][2];
#pragma unroll
        for (int u = 0; u < 2; u++)
#pragma unroll
            for (int v = 0; v < 2; v++)
                bb1[u][v] = sB1[(2 * u + v) * 64 + wc * 8 + g];

        float c10 = 0.f, c11 = 0.f;
        float acc[2][4];

        // x pipeline: warp = batch row wc, lane = 4 floats; 2-step LDG slack
        const int xr = wc, xi = lane * 4;
        const float* xrow = x + ((size_t)(b0r + xr) * T_) * I_ + xi;
        float4 xpA = *(const float4*)(xrow + 4 * (size_t)I_);   // x(4)
        float4 xpB = *(const float4*)(xrow + 5 * (size_t)I_);   // x(5)

        BARRIER();                                        // B(-1)

        for (int k = 0; k < T_; k++) {
            if (k) {
                // post-barrier: hh1 @ h1(k-2) (slot k&1) onto carried acc
                const half* H1r = sH1 + (k & 1) * HROW;
#pragma unroll
                for (int kt = 0; kt < 4; kt++) {
                    const half* q = H1r + g * SHS + kt * 16 + 2 * t;
                    uint32_t d0 = *(const uint32_t*)(q);
                    uint32_t d1 = *(const uint32_t*)(q + 8);
                    mma4(acc[0], fhh1[kt][0], d0, d1);
                    mma4(acc[1], fhh1[kt][1], d0, d1);
                }
                // L1 cell -> h1(k-1) into slot (k+1)&1
                float i0 = fsig(acc[0][0]), i1 = fsig(acc[0][1]);
                float f0 = fsig(acc[0][2]), f1 = fsig(acc[0][3]);
                float g0 = tanh_ap(acc[1][0]), g1 = tanh_ap(acc[1][1]);
                float o0 = fsig(acc[1][2]), o1 = fsig(acc[1][3]);
                c10 = f0 * c10 + i0 * g0;
                c11 = f1 * c11 + i1 * g1;
                half* h1w = sH1 + ((k + 1) & 1) * HROW;
                h1w[n0 * SHS + j]       = __float2half(o0 * tanh_ap(c10));
                h1w[(n0 + 1) * SHS + j] = __float2half(o1 * tanh_ap(c11));
            }
            // pre-barrier: carried acc = b1 + Wih1 @ h0(k)  (slot k&3)
            acc_set(acc, bb1);
            const half* H0r = sH0 + (k & 3) * HROW;
#pragma unroll
            for (int kt = 0; kt < 4; kt++) {
                const half* q = H0r + g * SHS + kt * 16 + 2 * t;
                uint32_t b0 = *(const uint32_t*)(q);
                uint32_t b1 = *(const uint32_t*)(q + 8);
                mma4(acc[0], fih1[kt][0], b0, b1);
                mma4(acc[1], fih1[kt][1], b0, b1);
            }
            {   // x pipeline: commit x(k+4) -> slot k&3, fetch x(k+6)
                half* xw = sX + (k & 3) * XROW;
                *(half2*)(xw + xr * SXS + xi)     = __floats2half2_rn(xpA.x, xpA.y);
                *(half2*)(xw + xr * SXS + xi + 2) = __floats2half2_rn(xpA.z, xpA.w);
                xpA = xpB;
                int tn = k + 6; if (tn > T_ - 1) tn = T_ - 1;
                xpB = *(const float4*)(xrow + (size_t)tn * I_);
            }
            BARRIER();                                    // B(k)
        }

        {   // epilogue: h1(T-1) = cell(carried ih1(h0(T-1)) + hh1 @ h1(T-2))
            const half* H1r = sH1 + 0 * HROW;             // h1(T-2): slot (T-2)&1 = 0
#pragma unroll
            for (int kt = 0; kt < 4; kt++) {
                const half* q = H1r + g * SHS + kt * 16 + 2 * t;
                uint32_t d0 = *(const uint32_t*)(q);
                uint32_t d1 = *(const uint32_t*)(q + 8);
                mma4(acc[0], fhh1[kt][0], d0, d1);
                mma4(acc[1], fhh1[kt][1], d0, d1);
            }
            float i0 = fsig(acc[0][0]), i1 = fsig(acc[0][1]);
            float f0 = fsig(acc[0][2]), f1 = fsig(acc[0][3]);
            float g0 = tanh_ap(acc[1][0]), g1 = tanh_ap(acc[1][1]);
            float o0 = fsig(acc[1][2]), o1 = fsig(acc[1][3]);
            c10 = f0 * c10 + i0 * g0;
            c11 = f1 * c11 + i1 * g1;
            sHF[n0 * H_ + j]       = o0 * tanh_ap(c10);
            sHF[(n0 + 1) * H_ + j] = o1 * tanh_ap(c11);
        }
    }

    __syncthreads();    // join: sHF complete before head

    // ---- head: proj -> relu -> fc1 -> relu -> fc2 ----
#pragma unroll
    for (int q = 0; q < 2; q++) {
        int idx = tid + q * NTHR;
        int r = idx >> 7, e = idx & 127;
        float a = bproj[e];
        const float* wp = Wproj + e * H_;
        const float* hp = sHF + r * H_;
#pragma unroll 8
        for (int kk = 0; kk < H_; kk++) a += hp[kk] * wp[kk];
        sE[r * E_ + e] = fmaxf(a, 0.f);
    }
    __syncthreads();
#pragma unroll
    for (int q = 0; q < 2; q++) {
        int idx = tid + q * NTHR;
        int r = idx >> 7, e = idx & 127;
        float a = bfc1[e];
        const float* wp = Wfc1 + e * E_;
        const float* hp = sE + r * E_;
#pragma unroll 8
        for (int kk = 0; kk < E_; kk++) a += hp[kk] * wp[kk];
        sF[r * E_ + e] = fmaxf(a, 0.f);
    }
    __syncthreads();
    for (int idx = tid; idx < BT * C_; idx += NTHR) {
        int r = idx / C_, c = idx - r * C_;
        float a = bfc2[c];
        const float* wp = Wfc2 + c * E_;
        const float* hp = sF + r * E_;
#pragma unroll 8
        for (int kk = 0; kk < E_; kk++) a += hp[kk] * wp[kk];
        out[(size_t)(b0r + r) * C_ + c] = a;
    }
}

}  // namespace

extern "C" void kernel_launch(void* const* d_in, const int* in_sizes, int n_in,
                              void* d_out, int out_size) {
    cudaFuncSetAttribute(lstm_fused, cudaFuncAttributeMaxDynamicSharedMemorySize,
                         SMEM_TOTAL);
    lstm_fused<<<NCTA, NTHR, SMEM_TOTAL>>>(
        (const float*)d_in[0],
        (const float*)d_in[1],  (const float*)d_in[2],
        (const float*)d_in[3],  (const float*)d_in[4],
        (const float*)d_in[5],  (const float*)d_in[6],
        (const float*)d_in[7],  (const float*)d_in[8],
        (const float*)d_in[9],  (const float*)d_in[10],
        (const float*)d_in[11], (const float*)d_in[12],
        (const float*)d_in[13], (const float*)d_in[14],
        (float*)d_out);
}